// round 13
// baseline (speedup 1.0000x reference)
#include <cuda_runtime.h>
#include <cuda_bf16.h>

// feeds: [N=65536, D=512] f32, rep: [N] int32 in [0,8), out: [S=262144, D] f32.
// out row j = feeds[i] where cumsum(rep) first exceeds j; rows >= total are 0.
//
// Pipeline:
//   1) scan_kernel: ONE block, 1024 threads. Tiles of 16384 ints; each thread
//      owns 16 contiguous ints (4 x int4), in-thread + warp + cross-warp scan,
//      carry across tiles, pipelined loads. Entire 256KB scan in one launch.
//   2) scatter_kernel (PDL): prefetches feeds row while scan finishes;
//      griddepsync before reading g_cum; r coalesced 2KB __stcs stores; tail.

#define MAX_N 65536
__device__ __align__(16) int g_cum[MAX_N];

__global__ void scan_kernel(const int4* __restrict__ rep4, int n) {
    __shared__ int ws[2][32];
    const int tid = threadIdx.x;
    const int lane = tid & 31, wid = tid >> 5;
    const int tiles = n >> 14;               // 16384 ints per tile

    int4 buf[4], nbuf[4];
    #pragma unroll
    for (int j = 0; j < 4; j++) buf[j] = __ldg(rep4 + tid * 4 + j);

    int running = 0;
    for (int k = 0; k < tiles; k++) {
        if (k + 1 < tiles) {
            #pragma unroll
            for (int j = 0; j < 4; j++)
                nbuf[j] = __ldg(rep4 + (k + 1) * 4096 + tid * 4 + j);
        }

        // In-thread inclusive scan of 16 contiguous values.
        int s[16];
        s[0] = buf[0].x;  s[1] = s[0] + buf[0].y;
        s[2] = s[1] + buf[0].z;  s[3] = s[2] + buf[0].w;
        #pragma unroll
        for (int j = 1; j < 4; j++) {
            s[4*j]   = s[4*j-1] + ((j==1)?buf[1].x:(j==2)?buf[2].x:buf[3].x);
            s[4*j+1] = s[4*j]   + ((j==1)?buf[1].y:(j==2)?buf[2].y:buf[3].y);
            s[4*j+2] = s[4*j+1] + ((j==1)?buf[1].z:(j==2)?buf[2].z:buf[3].z);
            s[4*j+3] = s[4*j+2] + ((j==1)?buf[1].w:(j==2)?buf[2].w:buf[3].w);
        }
        const int tot = s[15];

        // Warp-inclusive scan of thread totals.
        int inc = tot;
        #pragma unroll
        for (int off = 1; off < 32; off <<= 1) {
            int y = __shfl_up_sync(0xffffffffu, inc, off);
            if (lane >= off) inc += y;
        }
        const int texcl = inc - tot;
        if (lane == 31) ws[k & 1][wid] = inc;
        __syncthreads();
        if (wid == 0) {
            int w = ws[k & 1][lane];
            #pragma unroll
            for (int off = 1; off < 32; off <<= 1) {
                int y = __shfl_up_sync(0xffffffffu, w, off);
                if (lane >= off) w += y;
            }
            ws[k & 1][lane] = w;
        }
        __syncthreads();

        const int base = running + (wid > 0 ? ws[k & 1][wid - 1] : 0) + texcl;
        running += ws[k & 1][31];

        int4* cp = (int4*)g_cum + k * 4096 + tid * 4;
        cp[0] = make_int4(s[0]+base,  s[1]+base,  s[2]+base,  s[3]+base);
        cp[1] = make_int4(s[4]+base,  s[5]+base,  s[6]+base,  s[7]+base);
        cp[2] = make_int4(s[8]+base,  s[9]+base,  s[10]+base, s[11]+base);
        cp[3] = make_int4(s[12]+base, s[13]+base, s[14]+base, s[15]+base);

        #pragma unroll
        for (int j = 0; j < 4; j++) buf[j] = nbuf[j];
    }
    cudaTriggerProgrammaticLaunchCompletion();
}

// blocks [0, N): one per source row, 128 threads x float4 = one 2KB row.
// blocks [N, N+TAIL_BLOCKS): grid-stride zero of [total*d4, n4).
#define TAIL_BLOCKS 2048
__global__ void scatter_kernel(const float4* __restrict__ feeds,
                               const int* __restrict__ rep,
                               float4* __restrict__ out, int d4, int N,
                               size_t n4) {
    const int b = blockIdx.x;
    if (b < N) {
        const int r = __ldg(rep + b);
        // Prefetch the row (inputs only) while the scan may still be running.
        float4 v;
        if (r > 0) v = feeds[(size_t)b * d4 + threadIdx.x];
        cudaGridDependencySynchronize();   // g_cum now visible
        if (r == 0) return;
        const int start = g_cum[b] - r;
        float4* dst = out + (size_t)start * d4 + threadIdx.x;
        for (int k = 0; k < r; k++)
            __stcs(dst + (size_t)k * d4, v);
    } else {
        cudaGridDependencySynchronize();
        const int total = g_cum[N - 1];
        const size_t begin = (size_t)total * d4;
        const size_t tb = b - N;
        const size_t stride = (size_t)TAIL_BLOCKS * blockDim.x;
        const float4 z = make_float4(0.f, 0.f, 0.f, 0.f);
        for (size_t i = begin + tb * blockDim.x + threadIdx.x; i < n4;
             i += stride)
            __stcs(out + i, z);
    }
}

extern "C" void kernel_launch(void* const* d_in, const int* in_sizes, int n_in,
                              void* d_out, int out_size) {
    const float4* feeds = (const float4*)d_in[0];
    const int*    rep   = (const int*)d_in[1];
    float4*       out   = (float4*)d_out;

    const int N = in_sizes[1];                 // 65536 source rows
    const int D = in_sizes[0] / N;             // 512
    const int d4 = D / 4;                      // 128 float4 per row
    const int S = out_size / D;                // 262144 output rows
    const size_t n4 = (size_t)S * d4;

    // 1) full scan in a single block, single launch.
    scan_kernel<<<1, 1024>>>((const int4*)rep, N);

    // 2) scatter: PDL — prefetch overlaps scan tail; griddepsync gates g_cum.
    {
        cudaLaunchConfig_t cfg = {};
        cfg.gridDim = dim3(N + TAIL_BLOCKS);
        cfg.blockDim = dim3(d4);
        cudaLaunchAttribute at[1];
        at[0].id = cudaLaunchAttributeProgrammaticStreamSerialization;
        at[0].val.programmaticStreamSerializationAllowed = 1;
        cfg.attrs = at;
        cfg.numAttrs = 1;
        cudaLaunchKernelEx(&cfg, scatter_kernel, feeds, rep, out, d4, N, n4);
    }
}

// round 14
// speedup vs baseline: 1.0750x; 1.0750x over previous
#include <cuda_runtime.h>
#include <cuda_bf16.h>

// feeds: [N=65536, D=512] f32, rep: [N] int32 in [0,8), out: [S=262144, D] f32.
// out row j = feeds[i] where cumsum(rep) first exceeds j; rows >= total are 0.
//
// Pipeline:
//   1) scan_kernel: 64 blocks x 1024, single-pass scan with decoupled
//      lookback (all 64 blocks co-resident -> spin is safe).
//   2) scatter_kernel (PDL): prefetches feeds row while scan finishes;
//      griddepsync before reading g_cum; r coalesced 2KB __stcs stores;
//      tail zeroing; block N re-arms lookback flags for the next replay
//      (safe: griddepsync orders it after all scan-side flag reads).

#define MAX_N 65536
#define SCAN_BLOCKS 64
__device__ int g_cum[MAX_N];
__device__ int g_bsum[SCAN_BLOCKS];
__device__ volatile int g_flag[SCAN_BLOCKS];   // zero-init; reset by scatter

__global__ void scan_kernel(const int* __restrict__ rep) {
    __shared__ int ws[32];
    __shared__ int s_off;
    const int tid = threadIdx.x;
    const int lane = tid & 31, wid = tid >> 5;
    const int b = blockIdx.x;

    // Warp-level inclusive scan of own item.
    const int idx = b * 1024 + tid;
    int x = __ldg(rep + idx);
    #pragma unroll
    for (int off = 1; off < 32; off <<= 1) {
        int y = __shfl_up_sync(0xffffffffu, x, off);
        if (lane >= off) x += y;
    }
    if (lane == 31) ws[wid] = x;
    __syncthreads();

    if (wid == 0) {
        // Cross-warp inclusive scan; lane 31 now holds the block aggregate.
        int w = ws[lane];
        #pragma unroll
        for (int off = 1; off < 32; off <<= 1) {
            int y = __shfl_up_sync(0xffffffffu, w, off);
            if (lane >= off) w += y;
        }
        ws[lane] = w;
        if (lane == 31) {            // publish aggregate ASAP
            g_bsum[b] = w;
            __threadfence();
            g_flag[b] = 1;
        }
        // Lookback: sum aggregates of blocks [0, b).
        int v = 0;
        if (lane < b) {
            while (g_flag[lane] == 0) __nanosleep(20);
            v += g_bsum[lane];
        }
        if (lane + 32 < b) {
            while (g_flag[lane + 32] == 0) __nanosleep(20);
            v += g_bsum[lane + 32];
        }
        #pragma unroll
        for (int off = 16; off > 0; off >>= 1)
            v += __shfl_down_sync(0xffffffffu, v, off);
        if (lane == 0) s_off = v;
    }
    __syncthreads();

    g_cum[idx] = x + (wid > 0 ? ws[wid - 1] : 0) + s_off;
    cudaTriggerProgrammaticLaunchCompletion();
}

// blocks [0, N): one per source row, 128 threads x float4 = one 2KB row.
// blocks [N, N+TAIL_BLOCKS): grid-stride zero of [total*d4, n4).
// Block N re-arms the lookback flags (post-griddepsync => post-scan).
#define TAIL_BLOCKS 2048
__global__ void scatter_kernel(const float4* __restrict__ feeds,
                               const int* __restrict__ rep,
                               float4* __restrict__ out, int d4, int N,
                               size_t n4) {
    const int b = blockIdx.x;
    if (b < N) {
        const int r = __ldg(rep + b);
        // Prefetch the row (inputs only) while the scan may still be running.
        float4 v;
        if (r > 0) v = feeds[(size_t)b * d4 + threadIdx.x];
        cudaGridDependencySynchronize();   // g_cum now visible
        if (r == 0) return;
        const int start = g_cum[b] - r;
        float4* dst = out + (size_t)start * d4 + threadIdx.x;
        for (int k = 0; k < r; k++)
            __stcs(dst + (size_t)k * d4, v);
    } else {
        cudaGridDependencySynchronize();
        if (b == N && threadIdx.x < SCAN_BLOCKS)
            g_flag[threadIdx.x] = 0;       // re-arm for next graph replay
        const int total = g_cum[N - 1];
        const size_t begin = (size_t)total * d4;
        const size_t tb = b - N;
        const size_t stride = (size_t)TAIL_BLOCKS * blockDim.x;
        const float4 z = make_float4(0.f, 0.f, 0.f, 0.f);
        for (size_t i = begin + tb * blockDim.x + threadIdx.x; i < n4;
             i += stride)
            __stcs(out + i, z);
    }
}

extern "C" void kernel_launch(void* const* d_in, const int* in_sizes, int n_in,
                              void* d_out, int out_size) {
    const float4* feeds = (const float4*)d_in[0];
    const int*    rep   = (const int*)d_in[1];
    float4*       out   = (float4*)d_out;

    const int N = in_sizes[1];                 // 65536 source rows
    const int D = in_sizes[0] / N;             // 512
    const int d4 = D / 4;                      // 128 float4 per row
    const int S = out_size / D;                // 262144 output rows
    const size_t n4 = (size_t)S * d4;

    // 1) single-pass lookback scan, one launch.
    scan_kernel<<<SCAN_BLOCKS, 1024>>>(rep);

    // 2) scatter: PDL — prefetch overlaps scan; griddepsync gates g_cum.
    {
        cudaLaunchConfig_t cfg = {};
        cfg.gridDim = dim3(N + TAIL_BLOCKS);
        cfg.blockDim = dim3(d4);
        cudaLaunchAttribute at[1];
        at[0].id = cudaLaunchAttributeProgrammaticStreamSerialization;
        at[0].val.programmaticStreamSerializationAllowed = 1;
        cfg.attrs = at;
        cfg.numAttrs = 1;
        cudaLaunchKernelEx(&cfg, scatter_kernel, feeds, rep, out, d4, N, n4);
    }
}

// round 15
// speedup vs baseline: 1.1116x; 1.0340x over previous
#include <cuda_runtime.h>
#include <cuda_bf16.h>

// feeds: [N=65536, D=512] f32, rep: [N] int32 in [0,8), out: [S=262144, D] f32.
// out row j = feeds[i] where cumsum(rep) first exceeds j; rows >= total are 0.
//
// Pipeline (2 launches, PDL-chained):
//   1) sums_kernel: 64 blocks x 256 -> g_csum[1024] (64-int chunk sums) and
//      g_bsum[64] (1024-int segment sums). ~4.5us, hidden under scatter ramp.
//   2) scatter_kernel (PDL): each row-block computes its own exclusive prefix
//      from bsum + csum + <=16 int4 of raw rep (all L2-hot, warp-0 reduce,
//      overlapped with the feeds-row prefetch), then r coalesced 2KB __stcs
//      stores. Tail blocks zero [total, S).

#define SEGS 64
#define CHUNKS 1024
__device__ int g_bsum[SEGS];     // sums of 1024-int segments
__device__ int g_csum[CHUNKS];   // sums of 64-int chunks

// 64 blocks x 256 threads; thread t sums one int4; groups of 16 threads form
// one 64-int chunk sum; block sums 16 chunks -> one segment sum.
__global__ void sums_kernel(const int4* __restrict__ rep4) {
    __shared__ int gs[16];
    const int t = threadIdx.x, b = blockIdx.x;
    const int4 v = __ldg(rep4 + b * 256 + t);
    int s = v.x + v.y + v.z + v.w;
    #pragma unroll
    for (int off = 8; off > 0; off >>= 1)
        s += __shfl_down_sync(0xffffffffu, s, off);
    if ((t & 15) == 0) {                  // lanes 0,16 of each warp
        g_csum[b * 16 + (t >> 4)] = s;
        gs[t >> 4] = s;
    }
    __syncthreads();
    if (t == 0) {
        int tot = 0;
        #pragma unroll
        for (int i = 0; i < 16; i++) tot += gs[i];
        g_bsum[b] = tot;
    }
}

// blocks [0, N): one per source row, 128 threads x float4 = one 2KB row.
// blocks [N, N+TAIL_BLOCKS): grid-stride zero of [total*d4, n4).
#define TAIL_BLOCKS 2048
__global__ void scatter_kernel(const float4* __restrict__ feeds,
                               const int* __restrict__ rep,
                               float4* __restrict__ out, int d4, int N,
                               size_t n4) {
    __shared__ int s_val;
    const int b = blockIdx.x;
    const int tid = threadIdx.x;

    if (b < N) {
        const int r = __ldg(rep + b);
        // Prefetch the row (inputs only) while sums_kernel may still run.
        float4 v;
        if (r > 0) v = feeds[(size_t)b * d4 + tid];
        cudaGridDependencySynchronize();   // g_bsum/g_csum now visible
        if (r == 0) return;

        // Warp 0: exclusive prefix of rep[0..b) from the hierarchy.
        if (tid < 32) {
            const int seg = b >> 10;           // 1024-int segment
            const int f = b >> 6;              // 64-int chunk
            const int rem = b & 63;            // ints inside chunk f before b
            int acc = 0;
            if (tid < seg) acc += __ldg(&g_bsum[tid]);
            if (tid + 32 < seg) acc += __ldg(&g_bsum[tid + 32]);
            const int cbase = seg * 16;
            if (tid < (f - cbase)) acc += __ldg(&g_csum[cbase + tid]);
            const int full = rem >> 2, left = rem & 3;
            if (tid < full) {
                const int4 q = __ldg((const int4*)rep + f * 16 + tid);
                acc += q.x + q.y + q.z + q.w;
            } else if (tid == full && left) {
                const int* p = rep + f * 64 + full * 4;
                acc += p[0] + (left > 1 ? p[1] : 0) + (left > 2 ? p[2] : 0);
            }
            #pragma unroll
            for (int off = 16; off > 0; off >>= 1)
                acc += __shfl_down_sync(0xffffffffu, acc, off);
            if (tid == 0) s_val = acc;
        }
        __syncthreads();

        const int start = s_val;
        float4* dst = out + (size_t)start * d4 + tid;
        for (int k = 0; k < r; k++)
            __stcs(dst + (size_t)k * d4, v);
    } else {
        cudaGridDependencySynchronize();
        if (tid < 32) {
            int acc = __ldg(&g_bsum[tid]) + __ldg(&g_bsum[tid + 32]);
            #pragma unroll
            for (int off = 16; off > 0; off >>= 1)
                acc += __shfl_down_sync(0xffffffffu, acc, off);
            if (tid == 0) s_val = acc;
        }
        __syncthreads();
        const int total = s_val;
        const size_t begin = (size_t)total * d4;
        const size_t tb = b - N;
        const size_t stride = (size_t)TAIL_BLOCKS * blockDim.x;
        const float4 z = make_float4(0.f, 0.f, 0.f, 0.f);
        for (size_t i = begin + tb * blockDim.x + tid; i < n4; i += stride)
            __stcs(out + i, z);
    }
}

extern "C" void kernel_launch(void* const* d_in, const int* in_sizes, int n_in,
                              void* d_out, int out_size) {
    const float4* feeds = (const float4*)d_in[0];
    const int*    rep   = (const int*)d_in[1];
    float4*       out   = (float4*)d_out;

    const int N = in_sizes[1];                 // 65536 source rows
    const int D = in_sizes[0] / N;             // 512
    const int d4 = D / 4;                      // 128 float4 per row
    const int S = out_size / D;                // 262144 output rows
    const size_t n4 = (size_t)S * d4;

    // 1) hierarchical partial sums, one tiny launch.
    sums_kernel<<<SEGS, 256>>>((const int4*)rep);

    // 2) scatter: PDL — prefetch overlaps sums; griddepsync gates bsum/csum.
    {
        cudaLaunchConfig_t cfg = {};
        cfg.gridDim = dim3(N + TAIL_BLOCKS);
        cfg.blockDim = dim3(d4);
        cudaLaunchAttribute at[1];
        at[0].id = cudaLaunchAttributeProgrammaticStreamSerialization;
        at[0].val.programmaticStreamSerializationAllowed = 1;
        cfg.attrs = at;
        cfg.numAttrs = 1;
        cudaLaunchKernelEx(&cfg, scatter_kernel, feeds, rep, out, d4, N, n4);
    }
}

// round 16
// speedup vs baseline: 1.1187x; 1.0063x over previous
#include <cuda_runtime.h>
#include <cuda_bf16.h>

// feeds: [N=65536, D=512] f32, rep: [N] int32 in [0,8), out: [S=262144, D] f32.
// out row j = feeds[i] where cumsum(rep) first exceeds j; rows >= total are 0.
//
// Pipeline (2 launches, PDL-chained):
//   1) sums_kernel: 64 blocks x 256 -> g_csum[1024] (64-int chunk sums) and
//      g_bsum[64] (1024-int segment sums).
//   2) scatter_kernel (PDL): 512-thread blocks, 4 source rows per block.
//      One hierarchical exclusive-prefix per block (warp 0), per-row offsets
//      derived from the rows' own rep int4. r coalesced 2KB __stcs stores
//      per row. Tail blocks zero [total, S).

#define SEGS 64
#define CHUNKS 1024
__device__ int g_bsum[SEGS];     // sums of 1024-int segments
__device__ int g_csum[CHUNKS];   // sums of 64-int chunks

// 64 blocks x 256 threads; thread t sums one int4; groups of 16 threads form
// one 64-int chunk sum; block sums 16 chunks -> one segment sum.
__global__ void sums_kernel(const int4* __restrict__ rep4) {
    __shared__ int gs[16];
    const int t = threadIdx.x, b = blockIdx.x;
    const int4 v = __ldg(rep4 + b * 256 + t);
    int s = v.x + v.y + v.z + v.w;
    #pragma unroll
    for (int off = 8; off > 0; off >>= 1)
        s += __shfl_down_sync(0xffffffffu, s, off);
    if ((t & 15) == 0) {
        g_csum[b * 16 + (t >> 4)] = s;
        gs[t >> 4] = s;
    }
    __syncthreads();
    if (t == 0) {
        int tot = 0;
        #pragma unroll
        for (int i = 0; i < 16; i++) tot += gs[i];
        g_bsum[b] = tot;
    }
}

// blocks [0, N/4): 4 source rows each (512 threads, 1 float4/thread).
// blocks [N/4, N/4+TAIL_BLOCKS): grid-stride zero of [total*d4, n4).
#define TAIL_BLOCKS 1024
__global__ void scatter_kernel(const float4* __restrict__ feeds,
                               const int* __restrict__ rep,
                               float4* __restrict__ out, int d4, int N,
                               size_t n4) {
    __shared__ int s_start[4];
    const int g = blockIdx.x;
    const int tid = threadIdx.x;
    const int ngrp = N >> 2;

    if (g < ngrp) {
        const int row0 = g << 2;
        const int sub = tid >> 7;          // which of the 4 rows
        const int col = tid & 127;         // float4 lane within row
        const int4 q = __ldg((const int4*)rep + g);   // reps of rows 0..3
        const int myr = (sub == 0) ? q.x : (sub == 1) ? q.y
                      : (sub == 2) ? q.z : q.w;
        // Prefetch own row element (inputs only) while sums_kernel runs.
        float4 v;
        if (myr > 0) v = feeds[(size_t)(row0 + sub) * d4 + col];
        cudaGridDependencySynchronize();   // g_bsum/g_csum now visible

        // Warp 0: exclusive prefix of rep[0..row0) from the hierarchy.
        if (tid < 32) {
            const int seg = row0 >> 10;
            const int f = row0 >> 6;
            const int rem = row0 & 63;     // multiple of 4
            int acc = 0;
            if (tid < seg) acc += __ldg(&g_bsum[tid]);
            if (tid + 32 < seg) acc += __ldg(&g_bsum[tid + 32]);
            const int cbase = seg * 16;
            if (tid < (f - cbase)) acc += __ldg(&g_csum[cbase + tid]);
            const int full = rem >> 2;     // whole int4s before row0 in chunk
            if (tid < full) {
                const int4 p = __ldg((const int4*)rep + f * 16 + tid);
                acc += p.x + p.y + p.z + p.w;
            }
            #pragma unroll
            for (int off = 16; off > 0; off >>= 1)
                acc += __shfl_down_sync(0xffffffffu, acc, off);
            if (tid == 0) {
                s_start[0] = acc;
                s_start[1] = acc + q.x;
                s_start[2] = acc + q.x + q.y;
                s_start[3] = acc + q.x + q.y + q.z;
            }
        }
        __syncthreads();

        if (myr == 0) return;
        const int start = s_start[sub];
        float4* dst = out + (size_t)start * d4 + col;
        for (int k = 0; k < myr; k++)
            __stcs(dst + (size_t)k * d4, v);
    } else {
        cudaGridDependencySynchronize();
        __shared__ int s_total;
        if (tid < 32) {
            int acc = __ldg(&g_bsum[tid]) + __ldg(&g_bsum[tid + 32]);
            #pragma unroll
            for (int off = 16; off > 0; off >>= 1)
                acc += __shfl_down_sync(0xffffffffu, acc, off);
            if (tid == 0) s_total = acc;
        }
        __syncthreads();
        const size_t begin = (size_t)s_total * d4;
        const size_t tb = g - ngrp;
        const size_t stride = (size_t)TAIL_BLOCKS * blockDim.x;
        const float4 z = make_float4(0.f, 0.f, 0.f, 0.f);
        for (size_t i = begin + tb * blockDim.x + tid; i < n4; i += stride)
            __stcs(out + i, z);
    }
}

extern "C" void kernel_launch(void* const* d_in, const int* in_sizes, int n_in,
                              void* d_out, int out_size) {
    const float4* feeds = (const float4*)d_in[0];
    const int*    rep   = (const int*)d_in[1];
    float4*       out   = (float4*)d_out;

    const int N = in_sizes[1];                 // 65536 source rows
    const int D = in_sizes[0] / N;             // 512
    const int d4 = D / 4;                      // 128 float4 per row
    const int S = out_size / D;                // 262144 output rows
    const size_t n4 = (size_t)S * d4;

    sums_kernel<<<SEGS, 256>>>((const int4*)rep);

    {
        cudaLaunchConfig_t cfg = {};
        cfg.gridDim = dim3(N / 4 + TAIL_BLOCKS);
        cfg.blockDim = dim3(4 * d4);           // 512
        cudaLaunchAttribute at[1];
        at[0].id = cudaLaunchAttributeProgrammaticStreamSerialization;
        at[0].val.programmaticStreamSerializationAllowed = 1;
        cfg.attrs = at;
        cfg.numAttrs = 1;
        cudaLaunchKernelEx(&cfg, scatter_kernel, feeds, rep, out, d4, N, n4);
    }
}